// round 1
// baseline (speedup 1.0000x reference)
#include <cuda_runtime.h>

#define CE     768
#define NHEAD  8
#define HD     96
#define BATCH  8
#define SEQ    1024
#define MROWS  (BATCH*SEQ)

// Scratch (allocation-free rule: __device__ globals)
__device__ float g_q[BATCH*NHEAD*SEQ*HD];
__device__ float g_k[BATCH*NHEAD*SEQ*HD];
__device__ float g_v[BATCH*NHEAD*SEQ*HD];
__device__ float g_att[MROWS*CE];

// ---------------------------------------------------------------------------
// 128x128 fp32 GEMM, 8x8 microtile, 256 threads.
// scatter==1: epilogue scatters qkv columns into g_q/g_k/g_v [B,H,T,D].
// scatter==0: plain row-major store to Cout.
// ---------------------------------------------------------------------------
__global__ __launch_bounds__(256) void gemm_kernel(
    const float* __restrict__ A, const float* __restrict__ Bm,
    float* __restrict__ Cout, int N, int K, int scatter)
{
    __shared__ __align__(16) float As[16][132];
    __shared__ __align__(16) float Bs[16][132];
    const int t  = threadIdx.x;
    const int tx = t & 15, ty = t >> 4;
    const int mbase = blockIdx.y * 128;
    const int nbase = blockIdx.x * 128;

    float acc[8][8];
#pragma unroll
    for (int i = 0; i < 8; i++)
#pragma unroll
        for (int j = 0; j < 8; j++) acc[i][j] = 0.f;

    for (int kt = 0; kt < K; kt += 16) {
#pragma unroll
        for (int i = 0; i < 8; i++) {
            int idx = t + i * 256;             // 0..2047
            int r = idx >> 4, c = idx & 15;    // A tile 128x16, stored transposed
            As[c][r] = A[(mbase + r) * K + kt + c];
        }
#pragma unroll
        for (int i = 0; i < 8; i++) {
            int idx = t + i * 256;
            int r = idx >> 7, c = idx & 127;   // B tile 16x128
            Bs[r][c] = Bm[(kt + r) * N + nbase + c];
        }
        __syncthreads();
#pragma unroll
        for (int k = 0; k < 16; k++) {
            float4 a0 = *(const float4*)&As[k][ty * 8];
            float4 a1 = *(const float4*)&As[k][ty * 8 + 4];
            float4 b0 = *(const float4*)&Bs[k][tx * 8];
            float4 b1 = *(const float4*)&Bs[k][tx * 8 + 4];
            float a[8] = {a0.x,a0.y,a0.z,a0.w,a1.x,a1.y,a1.z,a1.w};
            float b[8] = {b0.x,b0.y,b0.z,b0.w,b1.x,b1.y,b1.z,b1.w};
#pragma unroll
            for (int i = 0; i < 8; i++)
#pragma unroll
                for (int j = 0; j < 8; j++)
                    acc[i][j] += a[i] * b[j];
        }
        __syncthreads();
    }

    if (scatter) {
#pragma unroll
        for (int i = 0; i < 8; i++) {
            int row = mbase + ty * 8 + i;          // b*SEQ + t
            int bb = row >> 10, tt = row & 1023;
#pragma unroll
            for (int j = 0; j < 8; j++) {
                int c = nbase + tx * 8 + j;        // 0..2303
                int which = c / CE;
                int cc = c - which * CE;
                int h = cc / HD, d = cc - h * HD;
                float* dst = (which == 0) ? g_q : (which == 1) ? g_k : g_v;
                dst[((bb * NHEAD + h) * SEQ + tt) * HD + d] = acc[i][j];
            }
        }
    } else {
#pragma unroll
        for (int i = 0; i < 8; i++) {
            int row = mbase + ty * 8 + i;
#pragma unroll
            for (int j = 0; j < 8; j++)
                Cout[row * N + nbase + tx * 8 + j] = acc[i][j];
        }
    }
}

// ---------------------------------------------------------------------------
// Flash attention fp32. BM=BN=32, 128 threads.
// Thread (row = tid/4, cg = tid%4): row owns 1 query row; cg splits the 32
// key scores (8 each) and the 96 output dims (24 each).
// K stored transposed in smem (Kt[d][j]) so the score loop does float4 LDS.
// ---------------------------------------------------------------------------
#define BM 32
#define BN 32

__global__ __launch_bounds__(128) void flash_kernel(float* __restrict__ out)
{
    __shared__ __align__(16) float Qs[BM][100];
    __shared__ __align__(16) float Kt[HD][36];
    __shared__ __align__(16) float Vs[BN][100];
    __shared__ __align__(16) float Ps[BM][36];

    const int bh  = blockIdx.y;                  // b*NHEAD + h
    const int qt  = blockIdx.x;
    const int tid = threadIdx.x;
    const int row = tid >> 2;                    // 0..31
    const int cg  = tid & 3;                     // 0..3
    const float scale = 0.10206207261596575f;    // 1/sqrt(96)

    const int q0 = qt * BM;
    const float* Qg = g_q + bh * SEQ * HD;
    const float* Kg = g_k + bh * SEQ * HD;
    const float* Vg = g_v + bh * SEQ * HD;

    // Load Q tile
    for (int idx = tid; idx < BM * HD; idx += 128) {
        int r = idx / HD, d = idx - r * HD;
        Qs[r][d] = Qg[(q0 + r) * HD + d];
    }

    float acc[24];
#pragma unroll
    for (int c = 0; c < 24; c++) acc[c] = 0.f;
    float m = -1e30f, l = 0.f;

    const int nkt = qt + 1;                      // causal: tiles up to diagonal
    for (int kt = 0; kt < nkt; kt++) {
        const int k0 = kt * BN;
        __syncthreads();                          // protect smem from prev iter
        for (int idx = tid; idx < BN * HD; idx += 128) {
            int r = idx / HD, d = idx - r * HD;
            Kt[d][r]  = Kg[(k0 + r) * HD + d];    // transposed
            Vs[r][d]  = Vg[(k0 + r) * HD + d];
        }
        __syncthreads();

        // Scores: 8 keys per thread, j = cg*8 + jj
        float s[8];
#pragma unroll
        for (int jj = 0; jj < 8; jj++) s[jj] = 0.f;
        for (int d = 0; d < HD; d++) {
            float q = Qs[row][d];
            float4 k0v = *(const float4*)&Kt[d][cg * 8];
            float4 k1v = *(const float4*)&Kt[d][cg * 8 + 4];
            s[0] += q * k0v.x; s[1] += q * k0v.y; s[2] += q * k0v.z; s[3] += q * k0v.w;
            s[4] += q * k1v.x; s[5] += q * k1v.y; s[6] += q * k1v.z; s[7] += q * k1v.w;
        }
        float mloc = -1e30f;
#pragma unroll
        for (int jj = 0; jj < 8; jj++) {
            int j = k0 + cg * 8 + jj;
            float v = s[jj] * scale;
            if (j > q0 + row) v = -1e30f;         // causal mask
            s[jj] = v;
            mloc = fmaxf(mloc, v);
        }
        mloc = fmaxf(mloc, __shfl_xor_sync(0xffffffffu, mloc, 1, 4));
        mloc = fmaxf(mloc, __shfl_xor_sync(0xffffffffu, mloc, 2, 4));
        float mnew  = fmaxf(m, mloc);
        float alpha = __expf(m - mnew);
        float psum = 0.f;
#pragma unroll
        for (int jj = 0; jj < 8; jj++) {
            float p = __expf(s[jj] - mnew);
            Ps[row][cg * 8 + jj] = p;
            psum += p;
        }
        psum += __shfl_xor_sync(0xffffffffu, psum, 1, 4);
        psum += __shfl_xor_sync(0xffffffffu, psum, 2, 4);
        l = l * alpha + psum;
        m = mnew;
#pragma unroll
        for (int c = 0; c < 24; c++) acc[c] *= alpha;
        __syncthreads();

        // PV: acc[0..23] covers output dims cg*24 .. cg*24+23
#pragma unroll 4
        for (int j = 0; j < BN; j++) {
            float p = Ps[row][j];
#pragma unroll
            for (int u = 0; u < 6; u++) {
                float4 v = *(const float4*)&Vs[j][cg * 24 + u * 4];
                acc[u * 4 + 0] += p * v.x;
                acc[u * 4 + 1] += p * v.y;
                acc[u * 4 + 2] += p * v.z;
                acc[u * 4 + 3] += p * v.w;
            }
        }
    }

    // Write to g_att in [B,T,C] layout
    const int b_ = bh / NHEAD, h_ = bh % NHEAD;
    const float inv_l = 1.f / l;
    const int grow = b_ * SEQ + q0 + row;
    float* dst = out + grow * CE + h_ * HD + cg * 24;
#pragma unroll
    for (int u = 0; u < 6; u++) {
        float4 o;
        o.x = acc[u * 4 + 0] * inv_l;
        o.y = acc[u * 4 + 1] * inv_l;
        o.z = acc[u * 4 + 2] * inv_l;
        o.w = acc[u * 4 + 3] * inv_l;
        *(float4*)&dst[u * 4] = o;
    }
}

// ---------------------------------------------------------------------------
extern "C" void kernel_launch(void* const* d_in, const int* in_sizes, int n_in,
                              void* d_out, int out_size)
{
    const float* x  = (const float*)d_in[0];   // [8,1024,768]
    const float* Wa = (const float*)d_in[1];   // [768,2304]
    const float* Wp = (const float*)d_in[2];   // [768,768]
    float* out = (float*)d_out;                // [8,1024,768]

    float* gatt;
    cudaGetSymbolAddress((void**)&gatt, g_att);

    // 1) QKV GEMM with scatter epilogue
    dim3 g1(3 * CE / 128, MROWS / 128);        // (18, 64)
    gemm_kernel<<<g1, 256>>>(x, Wa, nullptr, 3 * CE, CE, 1);

    // 2) Flash attention -> g_att [B,T,C]
    dim3 g2(SEQ / BM, BATCH * NHEAD);          // (32, 64)
    flash_kernel<<<g2, 128>>>(gatt);

    // 3) Output projection -> d_out
    dim3 g3(CE / 128, MROWS / 128);            // (6, 64)
    gemm_kernel<<<g3, 256>>>(gatt, Wp, out, CE, CE, 0);
}

// round 4
// speedup vs baseline: 1.8212x; 1.8212x over previous
#include <cuda_runtime.h>
#include <cuda_bf16.h>
#include <stdint.h>

#define CE     768
#define NHEAD  8
#define HD     96
#define BATCH  8
#define SEQ    1024
#define MROWS  (BATCH*SEQ)
#define KDIM   768
#define NQKV   (3*CE)
#define NK     (KDIM/16)

// ------------------------------- scratch (allocation-free rule) -------------
__device__ float g_q[BATCH*NHEAD*SEQ*HD];
__device__ float g_k[BATCH*NHEAD*SEQ*HD];
__device__ float g_v[BATCH*NHEAD*SEQ*HD];
__device__ __align__(16) __nv_bfloat16 g_xh[MROWS*KDIM];
__device__ __align__(16) __nv_bfloat16 g_xl[MROWS*KDIM];
__device__ __align__(16) __nv_bfloat16 g_wah[NQKV*KDIM];
__device__ __align__(16) __nv_bfloat16 g_wal[NQKV*KDIM];
__device__ __align__(16) __nv_bfloat16 g_wph[CE*KDIM];
__device__ __align__(16) __nv_bfloat16 g_wpl[CE*KDIM];
__device__ __align__(16) __nv_bfloat16 g_ah[MROWS*KDIM];
__device__ __align__(16) __nv_bfloat16 g_al[MROWS*KDIM];

// ------------------------------- helpers ------------------------------------
__device__ __forceinline__ uint32_t smem_u32(const void* p) {
    uint32_t a;
    asm("{ .reg .u64 t; cvta.to.shared.u64 t, %1; cvt.u32.u64 %0, t; }" : "=r"(a) : "l"(p));
    return a;
}
__device__ __forceinline__ void ldmx4(uint32_t* r, uint32_t addr) {
    asm volatile("ldmatrix.sync.aligned.m8n8.x4.shared.b16 {%0,%1,%2,%3}, [%4];"
                 : "=r"(r[0]), "=r"(r[1]), "=r"(r[2]), "=r"(r[3]) : "r"(addr));
}
__device__ __forceinline__ void mma16816(float* c, const uint32_t* a, const uint32_t* b) {
    asm volatile(
        "mma.sync.aligned.m16n8k16.row.col.f32.bf16.bf16.f32 "
        "{%0,%1,%2,%3}, {%4,%5,%6,%7}, {%8,%9}, {%0,%1,%2,%3};"
        : "+f"(c[0]), "+f"(c[1]), "+f"(c[2]), "+f"(c[3])
        : "r"(a[0]), "r"(a[1]), "r"(a[2]), "r"(a[3]), "r"(b[0]), "r"(b[1]));
}
__device__ __forceinline__ void cp16(uint32_t saddr, const void* gptr) {
    asm volatile("cp.async.ca.shared.global [%0], [%1], 16;"
                 :: "r"(saddr), "l"(__cvta_generic_to_global(gptr)) : "memory");
}
#define CP_COMMIT() asm volatile("cp.async.commit_group;" ::: "memory")
#define CP_WAIT1()  asm volatile("cp.async.wait_group 1;" ::: "memory")

// ------------------------------- conversion kernels -------------------------
__global__ void split_kernel(const float* __restrict__ in,
                             __nv_bfloat16* __restrict__ hi,
                             __nv_bfloat16* __restrict__ lo, int n)
{
    int i = (blockIdx.x * 256 + threadIdx.x) * 4;
    if (i >= n) return;
    float4 v = *(const float4*)(in + i);
    float f[4] = {v.x, v.y, v.z, v.w};
#pragma unroll
    for (int u = 0; u < 2; u++) {
        __nv_bfloat16 h0 = __float2bfloat16(f[2*u]);
        __nv_bfloat16 h1 = __float2bfloat16(f[2*u+1]);
        __nv_bfloat162 hp; hp.x = h0; hp.y = h1;
        __nv_bfloat162 lp;
        lp.x = __float2bfloat16(f[2*u]   - __bfloat162float(h0));
        lp.y = __float2bfloat16(f[2*u+1] - __bfloat162float(h1));
        *(__nv_bfloat162*)(hi + i + 2*u) = hp;
        *(__nv_bfloat162*)(lo + i + 2*u) = lp;
    }
}

// in: [K,N] row-major -> out hi/lo: [N,K] row-major (transposed) + split
__global__ void tsplit_kernel(const float* __restrict__ in,
                              __nv_bfloat16* __restrict__ hi,
                              __nv_bfloat16* __restrict__ lo, int K, int N)
{
    __shared__ float t[32][33];
    const int n0 = blockIdx.x * 32, k0 = blockIdx.y * 32;
#pragma unroll
    for (int i = 0; i < 4; i++) {
        int k = k0 + threadIdx.y + i * 8;
        t[threadIdx.y + i * 8][threadIdx.x] = in[(size_t)k * N + n0 + threadIdx.x];
    }
    __syncthreads();
#pragma unroll
    for (int i = 0; i < 4; i++) {
        int n = n0 + threadIdx.y + i * 8;
        float v = t[threadIdx.x][threadIdx.y + i * 8];
        __nv_bfloat16 h = __float2bfloat16(v);
        size_t o = (size_t)n * K + k0 + threadIdx.x;
        hi[o] = h;
        lo[o] = __float2bfloat16(v - __bfloat162float(h));
    }
}

// ------------------------------- HMMA GEMM ----------------------------------
// C[M,N] = (Ah+Al)[M,768] * (Bh+Bl)[N,768]^T, 3-pass split-bf16, fp32 accum.
// Block 128x128, 8 warps (4M x 2N), K-chunk 16, cp.async double buffer.
// smem layout per matrix chunk: addr(r, ch) = (r/8)*256 + (r%8)*16 + ch*128.
__global__ __launch_bounds__(256) void gemm_mma(
    const __nv_bfloat16* __restrict__ Ah, const __nv_bfloat16* __restrict__ Al,
    const __nv_bfloat16* __restrict__ Bh, const __nv_bfloat16* __restrict__ Bl,
    float* __restrict__ outp, int scatter)
{
    __shared__ __align__(128) uint8_t sm[2][4][4096];   // [stage][Ah,Al,Bh,Bl]
    const int tid = threadIdx.x, lid = tid & 31, wid = tid >> 5;
    const int wm = wid & 3, wn = wid >> 2;
    const int mbase = blockIdx.y * 128, nbase = blockIdx.x * 128;
    const uint32_t sbase = smem_u32(sm);

    // loader mapping: thread -> (row r, 16B chunk ch)
    const int r = tid >> 1, ch = tid & 1;
    const uint32_t so = ((r >> 3) << 8) | ((r & 7) << 4) | (ch << 7);
    const __nv_bfloat16* pAh = Ah + (size_t)(mbase + r) * KDIM + ch * 8;
    const __nv_bfloat16* pAl = Al + (size_t)(mbase + r) * KDIM + ch * 8;
    const __nv_bfloat16* pBh = Bh + (size_t)(nbase + r) * KDIM + ch * 8;
    const __nv_bfloat16* pBl = Bl + (size_t)(nbase + r) * KDIM + ch * 8;

    // ldmatrix lane offsets
    const uint32_t aoff = ((lid & 7) << 4) | (((lid >> 3) & 1) << 8) | ((lid >> 4) << 7);
    const uint32_t boff = ((lid & 7) << 4) | (((lid >> 3) & 1) << 7) | ((lid >> 4) << 8);

    float acc[2][8][4];
#pragma unroll
    for (int mt = 0; mt < 2; mt++)
#pragma unroll
        for (int nt = 0; nt < 8; nt++)
#pragma unroll
            for (int u = 0; u < 4; u++) acc[mt][nt][u] = 0.f;

    // prefetch stage 0
    {
        uint32_t sb = sbase + so;
        cp16(sb,         pAh);
        cp16(sb + 4096,  pAl);
        cp16(sb + 8192,  pBh);
        cp16(sb + 12288, pBl);
        CP_COMMIT();
    }

    for (int c = 0; c < NK; c++) {
        if (c + 1 < NK) {
            uint32_t sb = sbase + ((c + 1) & 1) * 16384 + so;
            int ko = (c + 1) * 16;
            cp16(sb,         pAh + ko);
            cp16(sb + 4096,  pAl + ko);
            cp16(sb + 8192,  pBh + ko);
            cp16(sb + 12288, pBl + ko);
        }
        CP_COMMIT();
        CP_WAIT1();
        __syncthreads();

        const uint32_t base = sbase + (c & 1) * 16384;
        const uint32_t aAh = base + wm * 1024 + aoff;
        const uint32_t aAl = base + 4096 + wm * 1024 + aoff;
        const uint32_t aBh = base + 8192 + wn * 2048 + boff;
        const uint32_t aBl = base + 12288 + wn * 2048 + boff;

        uint32_t ah[2][4], al[2][4], bh[4][4], bl[4][4];
#pragma unroll
        for (int mt = 0; mt < 2; mt++) {
            ldmx4(ah[mt], aAh + mt * 512);
            ldmx4(al[mt], aAl + mt * 512);
        }
#pragma unroll
        for (int g = 0; g < 4; g++) {
            ldmx4(bh[g], aBh + g * 512);
            ldmx4(bl[g], aBl + g * 512);
        }
#pragma unroll
        for (int mt = 0; mt < 2; mt++)
#pragma unroll
            for (int g = 0; g < 4; g++) {
                mma16816(acc[mt][2*g],   ah[mt], &bh[g][0]);
                mma16816(acc[mt][2*g+1], ah[mt], &bh[g][2]);
                mma16816(acc[mt][2*g],   ah[mt], &bl[g][0]);
                mma16816(acc[mt][2*g+1], ah[mt], &bl[g][2]);
                mma16816(acc[mt][2*g],   al[mt], &bh[g][0]);
                mma16816(acc[mt][2*g+1], al[mt], &bh[g][2]);
            }
        __syncthreads();
    }

    // epilogue: direct float2 stores (pairs are contiguous columns)
    const int rowb = mbase + wm * 32 + (lid >> 2);
    const int colb = nbase + wn * 64 + 2 * (lid & 3);
#pragma unroll
    for (int mt = 0; mt < 2; mt++)
#pragma unroll
        for (int nt = 0; nt < 8; nt++) {
            int col = colb + nt * 8;
#pragma unroll
            for (int h2 = 0; h2 < 2; h2++) {          // c0c1 then c2c3 (row+8)
                int row = rowb + mt * 16 + h2 * 8;
                float2 v = make_float2(acc[mt][nt][2*h2], acc[mt][nt][2*h2+1]);
                if (scatter) {
                    int which = col / CE, cc = col - which * CE;
                    int h = cc / HD, d = cc - h * HD;
                    float* dst = (which == 0) ? g_q : (which == 1) ? g_k : g_v;
                    int bb = row >> 10, tt = row & 1023;
                    *(float2*)(dst + (((bb * NHEAD + h) * SEQ) + tt) * HD + d) = v;
                } else {
                    *(float2*)(outp + (size_t)row * CE + col) = v;
                }
            }
        }
}

// ------------------------------- flash attention (fp32) ---------------------
// BM=64 (2 query rows per thread), BN=32, 128 threads.
#define BM 64
#define BN 32

__global__ __launch_bounds__(128) void flash_kernel()
{
    extern __shared__ float fsm[];
    float (*Qs)[100] = (float(*)[100])fsm;                  // 64 x 100
    float (*Kt)[36]  = (float(*)[36])(fsm + 6400);          // 96 x 36
    float (*Vs)[100] = (float(*)[100])(fsm + 6400 + 3456);  // 32 x 100
    float (*Ps)[36]  = (float(*)[36])(fsm + 6400 + 3456 + 3200); // 64 x 36

    const int bh  = blockIdx.y;
    const int qt  = gridDim.x - 1 - blockIdx.x;   // heavy tiles first
    const int tid = threadIdx.x;
    const int row = tid >> 2;                     // 0..31
    const int cg  = tid & 3;                      // 0..3
    const float scale = 0.10206207261596575f;     // 1/sqrt(96)

    const int q0 = qt * BM;
    const float* Qg = g_q + bh * SEQ * HD;
    const float* Kg = g_k + bh * SEQ * HD;
    const float* Vg = g_v + bh * SEQ * HD;

    for (int idx = tid; idx < BM * HD; idx += 128) {
        int rr = idx / HD, d = idx - rr * HD;
        Qs[rr][d] = Qg[(q0 + rr) * HD + d];
    }

    float acc0[24], acc1[24];
#pragma unroll
    for (int u = 0; u < 24; u++) { acc0[u] = 0.f; acc1[u] = 0.f; }
    float m0 = -1e30f, l0 = 0.f, m1 = -1e30f, l1 = 0.f;

    const int nkt = qt * 2 + 2;
    for (int kt = 0; kt < nkt; kt++) {
        const int k0 = kt * BN;
        __syncthreads();
        for (int idx = tid; idx < BN * HD; idx += 128) {
            int rr = idx / HD, d = idx - rr * HD;
            Kt[d][rr] = Kg[(k0 + rr) * HD + d];
            Vs[rr][d] = Vg[(k0 + rr) * HD + d];
        }
        __syncthreads();

        float s0[8], s1[8];
#pragma unroll
        for (int jj = 0; jj < 8; jj++) { s0[jj] = 0.f; s1[jj] = 0.f; }
        for (int d = 0; d < HD; d++) {
            float qa = Qs[row][d];
            float qb = Qs[row + 32][d];
            float4 k0v = *(const float4*)&Kt[d][cg * 8];
            float4 k1v = *(const float4*)&Kt[d][cg * 8 + 4];
            s0[0] += qa*k0v.x; s0[1] += qa*k0v.y; s0[2] += qa*k0v.z; s0[3] += qa*k0v.w;
            s0[4] += qa*k1v.x; s0[5] += qa*k1v.y; s0[6] += qa*k1v.z; s0[7] += qa*k1v.w;
            s1[0] += qb*k0v.x; s1[1] += qb*k0v.y; s1[2] += qb*k0v.z; s1[3] += qb*k0v.w;
            s1[4] += qb*k1v.x; s1[5] += qb*k1v.y; s1[6] += qb*k1v.z; s1[7] += qb*k1v.w;
        }

        float ml0 = -1e30f, ml1 = -1e30f;
#pragma unroll
        for (int jj = 0; jj < 8; jj++) {
            int j = k0 + cg * 8 + jj;
            float v0 = s0[jj] * scale, v1 = s1[jj] * scale;
            if (j > q0 + row)      v0 = -1e30f;
            if (j > q0 + row + 32) v1 = -1e30f;
            s0[jj] = v0; s1[jj] = v1;
            ml0 = fmaxf(ml0, v0); ml1 = fmaxf(ml1, v1);
        }
        ml0 = fmaxf(ml0, __shfl_xor_sync(0xffffffffu, ml0, 1, 4));
        ml0 = fmaxf(ml0, __shfl_xor_sync(0xffffffffu, ml0, 2, 4));
        ml1 = fmaxf(ml1, __shfl_xor_sync(0xffffffffu, ml1, 1, 4));
        ml1 = fmaxf(ml1, __shfl_xor_sync(0xffffffffu, ml1, 2, 4));
        float mn0 = fmaxf(m0, ml0), mn1 = fmaxf(m1, ml1);
        float al0 = __expf(m0 - mn0), al1 = __expf(m1 - mn1);
        float ps0 = 0.f, ps1 = 0.f;
#pragma unroll
        for (int jj = 0; jj < 8; jj++) {
            float p0 = __expf(s0[jj] - mn0);
            float p1 = __expf(s1[jj] - mn1);
            Ps[row][cg * 8 + jj]      = p0;
            Ps[row + 32][cg * 8 + jj] = p1;
            ps0 += p0; ps1 += p1;
        }
        ps0 += __shfl_xor_sync(0xffffffffu, ps0, 1, 4);
        ps0 += __shfl_xor_sync(0xffffffffu, ps0, 2, 4);
        ps1 += __shfl_xor_sync(0xffffffffu, ps1, 1, 4);
        ps1 += __shfl_xor_sync(0xffffffffu, ps1, 2, 4);
        l0 = l0 * al0 + ps0;  m0 = mn0;
        l1 = l1 * al1 + ps1;  m1 = mn1;
#pragma unroll
        for (int u = 0; u < 24; u++) { acc0[u] *= al0; acc1[u] *= al1; }
        __syncthreads();

#pragma unroll 4
        for (int j = 0; j < BN; j++) {
            float p0 = Ps[row][j];
            float p1 = Ps[row + 32][j];
#pragma unroll
            for (int u = 0; u < 6; u++) {
                float4 v = *(const float4*)&Vs[j][cg * 24 + u * 4];
                acc0[u*4+0] += p0*v.x; acc0[u*4+1] += p0*v.y;
                acc0[u*4+2] += p0*v.z; acc0[u*4+3] += p0*v.w;
                acc1[u*4+0] += p1*v.x; acc1[u*4+1] += p1*v.y;
                acc1[u*4+2] += p1*v.z; acc1[u*4+3] += p1*v.w;
            }
        }
    }

    // write split-bf16 attention output ([B,T,C] layout) for the proj GEMM
    const int b_ = bh / NHEAD, h_ = bh % NHEAD;
    const float il0 = 1.f / l0, il1 = 1.f / l1;
#pragma unroll
    for (int rr = 0; rr < 2; rr++) {
        const float* a = rr ? acc1 : acc0;
        const float il = rr ? il1 : il0;
        const int grow = b_ * SEQ + q0 + row + rr * 32;
        const int basei = grow * CE + h_ * HD + cg * 24;
#pragma unroll
        for (int u = 0; u < 24; u += 2) {
            float o0 = a[u] * il, o1 = a[u + 1] * il;
            __nv_bfloat16 h0 = __float2bfloat16(o0), h1 = __float2bfloat16(o1);
            __nv_bfloat162 hp; hp.x = h0; hp.y = h1;
            __nv_bfloat162 lp;
            lp.x = __float2bfloat16(o0 - __bfloat162float(h0));
            lp.y = __float2bfloat16(o1 - __bfloat162float(h1));
            *(__nv_bfloat162*)(g_ah + basei + u) = hp;
            *(__nv_bfloat162*)(g_al + basei + u) = lp;
        }
    }
}

// ---------------------------------------------------------------------------
extern "C" void kernel_launch(void* const* d_in, const int* in_sizes, int n_in,
                              void* d_out, int out_size)
{
    const float* x  = (const float*)d_in[0];   // [8,1024,768]
    const float* Wa = (const float*)d_in[1];   // [768,2304]
    const float* Wp = (const float*)d_in[2];   // [768,768]
    float* out = (float*)d_out;

    void *xh, *xl, *wah, *wal, *wph, *wpl, *ah, *al;
    cudaGetSymbolAddress(&xh,  g_xh);  cudaGetSymbolAddress(&xl,  g_xl);
    cudaGetSymbolAddress(&wah, g_wah); cudaGetSymbolAddress(&wal, g_wal);
    cudaGetSymbolAddress(&wph, g_wph); cudaGetSymbolAddress(&wpl, g_wpl);
    cudaGetSymbolAddress(&ah,  g_ah);  cudaGetSymbolAddress(&al,  g_al);

    cudaFuncSetAttribute(flash_kernel, cudaFuncAttributeMaxDynamicSharedMemorySize, 61440);

    // conversions
    split_kernel<<<(MROWS * KDIM) / 1024, 256>>>(x, (__nv_bfloat16*)xh, (__nv_bfloat16*)xl, MROWS * KDIM);
    dim3 bt(32, 8);
    tsplit_kernel<<<dim3(NQKV / 32, KDIM / 32), bt>>>(Wa, (__nv_bfloat16*)wah, (__nv_bfloat16*)wal, KDIM, NQKV);
    tsplit_kernel<<<dim3(CE / 32, KDIM / 32), bt>>>(Wp, (__nv_bfloat16*)wph, (__nv_bfloat16*)wpl, KDIM, CE);

    // 1) QKV GEMM (HMMA) with scatter epilogue
    gemm_mma<<<dim3(NQKV / 128, MROWS / 128), 256>>>(
        (__nv_bfloat16*)xh, (__nv_bfloat16*)xl,
        (__nv_bfloat16*)wah, (__nv_bfloat16*)wal, nullptr, 1);

    // 2) flash attention -> g_ah/g_al (split bf16, [B,T,C])
    flash_kernel<<<dim3(SEQ / BM, BATCH * NHEAD), 128, 61440>>>();

    // 3) output projection (HMMA) -> d_out
    gemm_mma<<<dim3(CE / 128, MROWS / 128), 256>>>(
        (__nv_bfloat16*)ah, (__nv_bfloat16*)al,
        (__nv_bfloat16*)wph, (__nv_bfloat16*)wpl, out, 0);
}

// round 5
// speedup vs baseline: 3.1533x; 1.7315x over previous
#include <cuda_runtime.h>
#include <cuda_bf16.h>
#include <stdint.h>

#define CE     768
#define NHEAD  8
#define HD     96
#define BATCH  8
#define SEQ    1024
#define MROWS  (BATCH*SEQ)
#define KDIM   768
#define NQKV   (3*CE)
#define NK     (KDIM/16)

// ------------------------------- scratch (allocation-free rule) -------------
__device__ __align__(16) __nv_bfloat16 g_xh[MROWS*KDIM];
__device__ __align__(16) __nv_bfloat16 g_xl[MROWS*KDIM];
__device__ __align__(16) __nv_bfloat16 g_wah[NQKV*KDIM];
__device__ __align__(16) __nv_bfloat16 g_wal[NQKV*KDIM];
__device__ __align__(16) __nv_bfloat16 g_wph[CE*KDIM];
__device__ __align__(16) __nv_bfloat16 g_wpl[CE*KDIM];
__device__ __align__(16) __nv_bfloat16 g_ah[MROWS*KDIM];
__device__ __align__(16) __nv_bfloat16 g_al[MROWS*KDIM];
__device__ __align__(16) __nv_bfloat16 g_qh[BATCH*NHEAD*SEQ*HD];
__device__ __align__(16) __nv_bfloat16 g_ql[BATCH*NHEAD*SEQ*HD];
__device__ __align__(16) __nv_bfloat16 g_kh[BATCH*NHEAD*SEQ*HD];
__device__ __align__(16) __nv_bfloat16 g_kl[BATCH*NHEAD*SEQ*HD];
__device__ __align__(16) __nv_bfloat16 g_vh[BATCH*NHEAD*SEQ*HD];
__device__ __align__(16) __nv_bfloat16 g_vl[BATCH*NHEAD*SEQ*HD];

// ------------------------------- helpers ------------------------------------
__device__ __forceinline__ uint32_t smem_u32(const void* p) {
    uint32_t a;
    asm("{ .reg .u64 t; cvta.to.shared.u64 t, %1; cvt.u32.u64 %0, t; }" : "=r"(a) : "l"(p));
    return a;
}
__device__ __forceinline__ void ldmx4(uint32_t* r, uint32_t addr) {
    asm volatile("ldmatrix.sync.aligned.m8n8.x4.shared.b16 {%0,%1,%2,%3}, [%4];"
                 : "=r"(r[0]), "=r"(r[1]), "=r"(r[2]), "=r"(r[3]) : "r"(addr));
}
__device__ __forceinline__ void ldmx4t(uint32_t* r, uint32_t addr) {
    asm volatile("ldmatrix.sync.aligned.m8n8.x4.trans.shared.b16 {%0,%1,%2,%3}, [%4];"
                 : "=r"(r[0]), "=r"(r[1]), "=r"(r[2]), "=r"(r[3]) : "r"(addr));
}
__device__ __forceinline__ void mma16816(float* c, const uint32_t* a, const uint32_t* b) {
    asm volatile(
        "mma.sync.aligned.m16n8k16.row.col.f32.bf16.bf16.f32 "
        "{%0,%1,%2,%3}, {%4,%5,%6,%7}, {%8,%9}, {%0,%1,%2,%3};"
        : "+f"(c[0]), "+f"(c[1]), "+f"(c[2]), "+f"(c[3])
        : "r"(a[0]), "r"(a[1]), "r"(a[2]), "r"(a[3]), "r"(b[0]), "r"(b[1]));
}
__device__ __forceinline__ void cp16(uint32_t saddr, const void* gptr) {
    asm volatile("cp.async.ca.shared.global [%0], [%1], 16;"
                 :: "r"(saddr), "l"(__cvta_generic_to_global(gptr)) : "memory");
}
#define CP_COMMIT() asm volatile("cp.async.commit_group;" ::: "memory")
#define CP_WAIT1()  asm volatile("cp.async.wait_group 1;" ::: "memory")

__device__ __forceinline__ void split2(float x, float y, uint32_t& hi, uint32_t& lo) {
    __nv_bfloat162 h, l;
    h.x = __float2bfloat16(x);  h.y = __float2bfloat16(y);
    l.x = __float2bfloat16(x - __bfloat162float(h.x));
    l.y = __float2bfloat16(y - __bfloat162float(h.y));
    hi = *(uint32_t*)&h;  lo = *(uint32_t*)&l;
}

// ------------------------------- conversion kernels -------------------------
__global__ void split_kernel(const float* __restrict__ in,
                             __nv_bfloat16* __restrict__ hi,
                             __nv_bfloat16* __restrict__ lo, int n)
{
    int i = (blockIdx.x * 256 + threadIdx.x) * 4;
    if (i >= n) return;
    float4 v = *(const float4*)(in + i);
    uint32_t h0, l0, h1, l1;
    split2(v.x, v.y, h0, l0);
    split2(v.z, v.w, h1, l1);
    *(uint32_t*)(hi + i)     = h0;  *(uint32_t*)(hi + i + 2) = h1;
    *(uint32_t*)(lo + i)     = l0;  *(uint32_t*)(lo + i + 2) = l1;
}

// in: [K,N] row-major -> out hi/lo: [N,K] row-major (transposed) + split
__global__ void tsplit_kernel(const float* __restrict__ in,
                              __nv_bfloat16* __restrict__ hi,
                              __nv_bfloat16* __restrict__ lo, int K, int N)
{
    __shared__ float t[32][33];
    const int n0 = blockIdx.x * 32, k0 = blockIdx.y * 32;
#pragma unroll
    for (int i = 0; i < 4; i++) {
        int k = k0 + threadIdx.y + i * 8;
        t[threadIdx.y + i * 8][threadIdx.x] = in[(size_t)k * N + n0 + threadIdx.x];
    }
    __syncthreads();
#pragma unroll
    for (int i = 0; i < 4; i++) {
        int n = n0 + threadIdx.y + i * 8;
        float v = t[threadIdx.x][threadIdx.y + i * 8];
        __nv_bfloat16 h = __float2bfloat16(v);
        size_t o = (size_t)n * K + k0 + threadIdx.x;
        hi[o] = h;
        lo[o] = __float2bfloat16(v - __bfloat162float(h));
    }
}

// ------------------------------- HMMA GEMM ----------------------------------
// C[M,N] = (Ah+Al)[M,768]*(Bh+Bl)[N,768]^T, 3-pass split-bf16, fp32 accum.
// Block 128x128, 8 warps (4Mx2N), K-chunk 16, cp.async double buffer.
__global__ __launch_bounds__(256) void gemm_mma(
    const __nv_bfloat16* __restrict__ Ah, const __nv_bfloat16* __restrict__ Al,
    const __nv_bfloat16* __restrict__ Bh, const __nv_bfloat16* __restrict__ Bl,
    float* __restrict__ outp, int scatter)
{
    __shared__ __align__(128) uint8_t sm[2][4][4096];
    const int tid = threadIdx.x, lid = tid & 31, wid = tid >> 5;
    const int wm = wid & 3, wn = wid >> 2;
    const int mbase = blockIdx.y * 128, nbase = blockIdx.x * 128;
    const uint32_t sbase = smem_u32(sm);

    const int r = tid >> 1, ch = tid & 1;
    const uint32_t so = ((r >> 3) << 8) | ((r & 7) << 4) | (ch << 7);
    const __nv_bfloat16* pAh = Ah + (size_t)(mbase + r) * KDIM + ch * 8;
    const __nv_bfloat16* pAl = Al + (size_t)(mbase + r) * KDIM + ch * 8;
    const __nv_bfloat16* pBh = Bh + (size_t)(nbase + r) * KDIM + ch * 8;
    const __nv_bfloat16* pBl = Bl + (size_t)(nbase + r) * KDIM + ch * 8;

    const uint32_t aoff = ((lid & 7) << 4) | (((lid >> 3) & 1) << 8) | ((lid >> 4) << 7);
    const uint32_t boff = ((lid & 7) << 4) | (((lid >> 3) & 1) << 7) | ((lid >> 4) << 8);

    float acc[2][8][4];
#pragma unroll
    for (int mt = 0; mt < 2; mt++)
#pragma unroll
        for (int nt = 0; nt < 8; nt++)
#pragma unroll
            for (int u = 0; u < 4; u++) acc[mt][nt][u] = 0.f;

    {
        uint32_t sb = sbase + so;
        cp16(sb, pAh); cp16(sb + 4096, pAl);
        cp16(sb + 8192, pBh); cp16(sb + 12288, pBl);
        CP_COMMIT();
    }

    for (int c = 0; c < NK; c++) {
        if (c + 1 < NK) {
            uint32_t sb = sbase + ((c + 1) & 1) * 16384 + so;
            int ko = (c + 1) * 16;
            cp16(sb, pAh + ko); cp16(sb + 4096, pAl + ko);
            cp16(sb + 8192, pBh + ko); cp16(sb + 12288, pBl + ko);
        }
        CP_COMMIT();
        CP_WAIT1();
        __syncthreads();

        const uint32_t base = sbase + (c & 1) * 16384;
        const uint32_t aAh = base + wm * 1024 + aoff;
        const uint32_t aAl = base + 4096 + wm * 1024 + aoff;
        const uint32_t aBh = base + 8192 + wn * 2048 + boff;
        const uint32_t aBl = base + 12288 + wn * 2048 + boff;

        uint32_t ah[2][4], al[2][4], bh[4][4], bl[4][4];
#pragma unroll
        for (int mt = 0; mt < 2; mt++) { ldmx4(ah[mt], aAh + mt * 512); ldmx4(al[mt], aAl + mt * 512); }
#pragma unroll
        for (int g = 0; g < 4; g++) { ldmx4(bh[g], aBh + g * 512); ldmx4(bl[g], aBl + g * 512); }
#pragma unroll
        for (int mt = 0; mt < 2; mt++)
#pragma unroll
            for (int g = 0; g < 4; g++) {
                mma16816(acc[mt][2*g],   ah[mt], &bh[g][0]);
                mma16816(acc[mt][2*g+1], ah[mt], &bh[g][2]);
                mma16816(acc[mt][2*g],   ah[mt], &bl[g][0]);
                mma16816(acc[mt][2*g+1], ah[mt], &bl[g][2]);
                mma16816(acc[mt][2*g],   al[mt], &bh[g][0]);
                mma16816(acc[mt][2*g+1], al[mt], &bh[g][2]);
            }
        __syncthreads();
    }

    const int rowb = mbase + wm * 32 + (lid >> 2);
    const int colb = nbase + wn * 64 + 2 * (lid & 3);
#pragma unroll
    for (int mt = 0; mt < 2; mt++)
#pragma unroll
        for (int nt = 0; nt < 8; nt++) {
            int col = colb + nt * 8;
#pragma unroll
            for (int h2 = 0; h2 < 2; h2++) {
                int row = rowb + mt * 16 + h2 * 8;
                float vx = acc[mt][nt][2*h2], vy = acc[mt][nt][2*h2+1];
                if (scatter) {
                    int which = col / CE, cc = col - which * CE;
                    int h = cc / HD, d = cc - h * HD;
                    int bb = row >> 10, tt = row & 1023;
                    size_t idx = (size_t)(((bb * NHEAD + h) * SEQ) + tt) * HD + d;
                    uint32_t hi, lo;
                    split2(vx, vy, hi, lo);
                    __nv_bfloat16 *dh, *dl;
                    if (which == 0)      { dh = g_qh; dl = g_ql; }
                    else if (which == 1) { dh = g_kh; dl = g_kl; }
                    else                 { dh = g_vh; dl = g_vl; }
                    *(uint32_t*)(dh + idx) = hi;
                    *(uint32_t*)(dl + idx) = lo;
                } else {
                    *(float2*)(outp + (size_t)row * CE + col) = make_float2(vx, vy);
                }
            }
        }
}

// ------------------------------- flash attention (HMMA) ---------------------
// BM=128 (8 warps x 16 rows), BN=64 key tiles, one (b,h) per blockIdx.y.
// Split-bf16 3-pass for S=QK^T and O+=PV; P kept in registers; V via ldmatrix.trans.
#define FBM    128
#define FBN    64
#define PITCHB 208                 // 96 bf16 = 192B data, padded (13x16B: conflict-free)
#define KVSTG  (4*FBN*PITCHB)      // Kh,Kl,Vh,Vl per stage = 53248
#define FSMEM  (2*FBM*PITCHB + 2*KVSTG)   // 159744

__global__ __launch_bounds__(256, 1) void flash_mma()
{
    extern __shared__ uint8_t fs[];
    const int tid = threadIdx.x, lid = tid & 31, wid = tid >> 5;
    const int bh = blockIdx.y;
    const int qt = (int)gridDim.x - 1 - (int)blockIdx.x;   // heavy tiles first
    const int q0 = qt * FBM;
    const uint32_t sQh = smem_u32(fs);
    const uint32_t sKV = sQh + 2 * FBM * PITCHB;
    const size_t gb = (size_t)bh * SEQ * HD;
    const float scale = 0.10206207261596575f;   // 1/sqrt(96)

    // KV loader mapping: row = tid>>2 (0..63), quarter = tid&3, 3 chunks each
    const int rkv = tid >> 2, qq = tid & 3;

    // stage-0 KV
    {
        uint32_t sb = sKV + rkv * PITCHB + qq * 48;
        size_t go = gb + (size_t)rkv * HD + qq * 24;
#pragma unroll
        for (int k = 0; k < 3; k++) {
            cp16(sb + k*16,                 g_kh + go + k*8);
            cp16(sb + FBN*PITCHB + k*16,    g_kl + go + k*8);
            cp16(sb + 2*FBN*PITCHB + k*16,  g_vh + go + k*8);
            cp16(sb + 3*FBN*PITCHB + k*16,  g_vl + go + k*8);
        }
    }
    CP_COMMIT();
    // Q (resident): row = tid>>1, half = tid&1, 6 chunks each
    {
        int r = tid >> 1, hf = tid & 1;
        uint32_t sq = sQh + r * PITCHB + hf * 96;
        size_t gq = gb + (size_t)(q0 + r) * HD + hf * 48;
#pragma unroll
        for (int k = 0; k < 6; k++) {
            cp16(sq + k*16,              g_qh + gq + k*8);
            cp16(sq + FBM*PITCHB + k*16, g_ql + gq + k*8);
        }
    }
    CP_COMMIT();

    const uint32_t aoff = (lid & 7) * PITCHB + ((lid >> 3) & 1) * (8 * PITCHB) + (lid >> 4) * 16;
    const uint32_t boff = (lid & 7) * PITCHB + ((lid >> 3) & 1) * 16 + (lid >> 4) * (8 * PITCHB);

    uint32_t qfh[6][4], qfl[6][4];
    float oacc[12][4];
#pragma unroll
    for (int n = 0; n < 12; n++)
#pragma unroll
        for (int u = 0; u < 4; u++) oacc[n][u] = 0.f;
    float m0 = -1e30f, m1 = -1e30f, lsum0 = 0.f, lsum1 = 0.f;
    const int row0 = q0 + wid * 16 + (lid >> 2);

    const int nkt = 2 * qt + 2;
    for (int kt = 0; kt < nkt; kt++) {
        if (kt + 1 < nkt) {
            uint32_t sb = sKV + ((kt + 1) & 1) * KVSTG + rkv * PITCHB + qq * 48;
            size_t go = gb + (size_t)((kt + 1) * FBN + rkv) * HD + qq * 24;
#pragma unroll
            for (int k = 0; k < 3; k++) {
                cp16(sb + k*16,                g_kh + go + k*8);
                cp16(sb + FBN*PITCHB + k*16,   g_kl + go + k*8);
                cp16(sb + 2*FBN*PITCHB + k*16, g_vh + go + k*8);
                cp16(sb + 3*FBN*PITCHB + k*16, g_vl + go + k*8);
            }
        }
        CP_COMMIT();
        CP_WAIT1();
        __syncthreads();

        if (kt == 0) {   // Q fragments, loaded once
            uint32_t aQ = sQh + wid * 16 * PITCHB + aoff;
#pragma unroll
            for (int kc = 0; kc < 6; kc++) {
                ldmx4(qfh[kc], aQ + kc * 32);
                ldmx4(qfl[kc], aQ + FBM * PITCHB + kc * 32);
            }
        }

        const uint32_t stg = sKV + (kt & 1) * KVSTG;

        // ---- S = Q K^T (3-pass)
        float sacc[8][4];
#pragma unroll
        for (int n = 0; n < 8; n++)
#pragma unroll
            for (int u = 0; u < 4; u++) sacc[n][u] = 0.f;
#pragma unroll
        for (int kc = 0; kc < 6; kc++) {
#pragma unroll
            for (int g = 0; g < 4; g++) {
                uint32_t kh4[4], kl4[4];
                ldmx4(kh4, stg + boff + g * (16 * PITCHB) + kc * 32);
                ldmx4(kl4, stg + FBN*PITCHB + boff + g * (16 * PITCHB) + kc * 32);
                mma16816(sacc[2*g],   qfh[kc], &kh4[0]);
                mma16816(sacc[2*g+1], qfh[kc], &kh4[2]);
                mma16816(sacc[2*g],   qfh[kc], &kl4[0]);
                mma16816(sacc[2*g+1], qfh[kc], &kl4[2]);
                mma16816(sacc[2*g],   qfl[kc], &kh4[0]);
                mma16816(sacc[2*g+1], qfl[kc], &kh4[2]);
            }
        }

        // ---- softmax (online)
        const int colb = kt * FBN + 2 * (lid & 3);
        float ml0 = -1e30f, ml1 = -1e30f;
#pragma unroll
        for (int n = 0; n < 8; n++)
#pragma unroll
            for (int e = 0; e < 2; e++) {
                int col = colb + 8 * n + e;
                float v0 = sacc[n][e] * scale;     if (col > row0)     v0 = -1e30f;
                float v1 = sacc[n][2 + e] * scale; if (col > row0 + 8) v1 = -1e30f;
                sacc[n][e] = v0; sacc[n][2 + e] = v1;
                ml0 = fmaxf(ml0, v0); ml1 = fmaxf(ml1, v1);
            }
        ml0 = fmaxf(ml0, __shfl_xor_sync(0xffffffffu, ml0, 1));
        ml0 = fmaxf(ml0, __shfl_xor_sync(0xffffffffu, ml0, 2));
        ml1 = fmaxf(ml1, __shfl_xor_sync(0xffffffffu, ml1, 1));
        ml1 = fmaxf(ml1, __shfl_xor_sync(0xffffffffu, ml1, 2));
        float mn0 = fmaxf(m0, ml0), mn1 = fmaxf(m1, ml1);
        float al0 = __expf(m0 - mn0), al1 = __expf(m1 - mn1);
        float ps0 = 0.f, ps1 = 0.f;
#pragma unroll
        for (int n = 0; n < 8; n++) {
            sacc[n][0] = __expf(sacc[n][0] - mn0); ps0 += sacc[n][0];
            sacc[n][1] = __expf(sacc[n][1] - mn0); ps0 += sacc[n][1];
            sacc[n][2] = __expf(sacc[n][2] - mn1); ps1 += sacc[n][2];
            sacc[n][3] = __expf(sacc[n][3] - mn1); ps1 += sacc[n][3];
        }
        ps0 += __shfl_xor_sync(0xffffffffu, ps0, 1);
        ps0 += __shfl_xor_sync(0xffffffffu, ps0, 2);
        ps1 += __shfl_xor_sync(0xffffffffu, ps1, 1);
        ps1 += __shfl_xor_sync(0xffffffffu, ps1, 2);
        lsum0 = lsum0 * al0 + ps0; m0 = mn0;
        lsum1 = lsum1 * al1 + ps1; m1 = mn1;
#pragma unroll
        for (int n = 0; n < 12; n++) {
            oacc[n][0] *= al0; oacc[n][1] *= al0;
            oacc[n][2] *= al1; oacc[n][3] *= al1;
        }

        // ---- O += P V  (3-pass; P from registers, V via ldmatrix.trans)
        const uint32_t vBh = stg + 2 * FBN * PITCHB + aoff;   // same lane formula as A
#pragma unroll
        for (int kc2 = 0; kc2 < 4; kc2++) {
            uint32_t pah[4], pal[4];
            split2(sacc[2*kc2][0],   sacc[2*kc2][1],   pah[0], pal[0]);
            split2(sacc[2*kc2][2],   sacc[2*kc2][3],   pah[1], pal[1]);
            split2(sacc[2*kc2+1][0], sacc[2*kc2+1][1], pah[2], pal[2]);
            split2(sacc[2*kc2+1][2], sacc[2*kc2+1][3], pah[3], pal[3]);
            uint32_t vb = vBh + kc2 * (16 * PITCHB);
#pragma unroll
            for (int dn = 0; dn < 6; dn++) {
                uint32_t vh4[4], vl4[4];
                ldmx4t(vh4, vb + dn * 32);
                ldmx4t(vl4, vb + FBN*PITCHB + dn * 32);
                mma16816(oacc[2*dn],   pah, &vh4[0]);
                mma16816(oacc[2*dn+1], pah, &vh4[2]);
                mma16816(oacc[2*dn],   pal, &vh4[0]);
                mma16816(oacc[2*dn+1], pal, &vh4[2]);
                mma16816(oacc[2*dn],   pah, &vl4[0]);
                mma16816(oacc[2*dn+1], pah, &vl4[2]);
            }
        }
        __syncthreads();
    }

    // ---- epilogue: O/l -> split-bf16 [B,T,C] for the projection GEMM
    const int b_ = bh >> 3, h_ = bh & 7;
    const float il0 = 1.f / lsum0, il1 = 1.f / lsum1;
    const size_t base0 = (size_t)(b_ * SEQ + row0) * CE + h_ * HD + 2 * (lid & 3);
    const size_t base1 = base0 + (size_t)8 * CE;
#pragma unroll
    for (int n = 0; n < 12; n++) {
        uint32_t hi, lo;
        split2(oacc[n][0] * il0, oacc[n][1] * il0, hi, lo);
        *(uint32_t*)(g_ah + base0 + 8 * n) = hi;
        *(uint32_t*)(g_al + base0 + 8 * n) = lo;
        split2(oacc[n][2] * il1, oacc[n][3] * il1, hi, lo);
        *(uint32_t*)(g_ah + base1 + 8 * n) = hi;
        *(uint32_t*)(g_al + base1 + 8 * n) = lo;
    }
}

// ---------------------------------------------------------------------------
extern "C" void kernel_launch(void* const* d_in, const int* in_sizes, int n_in,
                              void* d_out, int out_size)
{
    const float* x  = (const float*)d_in[0];   // [8,1024,768]
    const float* Wa = (const float*)d_in[1];   // [768,2304]
    const float* Wp = (const float*)d_in[2];   // [768,768]
    float* out = (float*)d_out;

    void *xh, *xl, *wah, *wal, *wph, *wpl, *ah, *al;
    cudaGetSymbolAddress(&xh,  g_xh);  cudaGetSymbolAddress(&xl,  g_xl);
    cudaGetSymbolAddress(&wah, g_wah); cudaGetSymbolAddress(&wal, g_wal);
    cudaGetSymbolAddress(&wph, g_wph); cudaGetSymbolAddress(&wpl, g_wpl);
    cudaGetSymbolAddress(&ah,  g_ah);  cudaGetSymbolAddress(&al,  g_al);

    cudaFuncSetAttribute(flash_mma, cudaFuncAttributeMaxDynamicSharedMemorySize, FSMEM);

    // conversions
    split_kernel<<<(MROWS * KDIM) / 1024, 256>>>(x, (__nv_bfloat16*)xh, (__nv_bfloat16*)xl, MROWS * KDIM);
    dim3 bt(32, 8);
    tsplit_kernel<<<dim3(NQKV / 32, KDIM / 32), bt>>>(Wa, (__nv_bfloat16*)wah, (__nv_bfloat16*)wal, KDIM, NQKV);
    tsplit_kernel<<<dim3(CE / 32, KDIM / 32), bt>>>(Wp, (__nv_bfloat16*)wph, (__nv_bfloat16*)wpl, KDIM, CE);

    // 1) QKV GEMM (HMMA) -> split-bf16 q/k/v [B,H,T,D]
    gemm_mma<<<dim3(NQKV / 128, MROWS / 128), 256>>>(
        (__nv_bfloat16*)xh, (__nv_bfloat16*)xl,
        (__nv_bfloat16*)wah, (__nv_bfloat16*)wal, nullptr, 1);

    // 2) flash attention (HMMA) -> g_ah/g_al (split bf16, [B,T,C])
    flash_mma<<<dim3(SEQ / FBM, BATCH * NHEAD), 256, FSMEM>>>();

    // 3) output projection (HMMA) -> d_out
    gemm_mma<<<dim3(CE / 128, MROWS / 128), 256>>>(
        (__nv_bfloat16*)ah, (__nv_bfloat16*)al,
        (__nv_bfloat16*)wph, (__nv_bfloat16*)wpl, out, 0);
}